// round 14
// baseline (speedup 1.0000x reference)
#include <cuda_runtime.h>
#include <cuda_fp16.h>
#include <math_constants.h>

#define N_TOK    16384
#define IN_FEAT  4096
#define N_EXP    64
#define CAPACITY 640
#define SPLITS   4
#define KSEG     (IN_FEAT / SPLITS)   // 1024
#define NSTEP    (KSEG / 16)          // 64 k-steps of 16
#define TH_GAP   1.5e-3f

// persistent scratch
__device__ __align__(16) uint4 g_Wfrag4[256 * 4 * 32];      // fp16 W frags, mma B layout
__device__ float          g_part[SPLITS * N_TOK * N_EXP];   // split-K partials
__device__ int            g_tilecnt[N_TOK / 64];
__device__ int            g_counts[N_EXP];
__device__ int            g_elist[(size_t)N_EXP * N_TOK];
__device__ int            g_topidx[2 * N_TOK];
__device__ float          g_topp[2 * N_TOK];
__device__ unsigned char  g_drop[2 * N_TOK];
__device__ int            g_nflag;
__device__ int            g_flaglist[N_TOK];
__device__ int            g_bar;

#define MMA(ACC, A0, A1, A2, A3, B0, B1) \
    asm volatile("mma.sync.aligned.m16n8k16.row.col.f32.f16.f16.f32 " \
        "{%0,%1,%2,%3}, {%4,%5,%6,%7}, {%8,%9}, {%0,%1,%2,%3};" \
        : "+f"((ACC)[0]), "+f"((ACC)[1]), "+f"((ACC)[2]), "+f"((ACC)[3]) \
        : "r"(A0), "r"(A1), "r"(A2), "r"(A3), "r"(B0), "r"(B1))

__global__ void dummy_kernel() {}

// ---------------------------------------------------------------------------
// prep: fp16 W fragments in mma.m16n8k16 B layout + init counters.
// ---------------------------------------------------------------------------
__global__ void prep_kernel(const float* __restrict__ W) {
    int idx = blockIdx.x * blockDim.x + threadIdx.x;   // 0 .. 65535
    if (idx < N_EXP) g_counts[idx] = 0;
    if (idx < 2 * N_TOK) g_drop[idx] = 0;
    if (idx < N_TOK / 64) g_tilecnt[idx] = 0;
    if (idx == 0) { g_nflag = 0; g_bar = 0; }

    int l = idx & 31;
    int t = (idx >> 5) & 7;
    int s = idx >> 8;                 // 0..255
    int n  = t * 8 + (l >> 2);
    int kb = s * 16 + (l & 3) * 2;
    const float* row = W + (size_t)n * IN_FEAT;
    __half2 p0 = __halves2half2(__float2half_rn(row[kb]),     __float2half_rn(row[kb + 1]));
    __half2 p1 = __halves2half2(__float2half_rn(row[kb + 8]), __float2half_rn(row[kb + 9]));
    uint2 o;
    o.x = *(unsigned*)&p0;
    o.y = *(unsigned*)&p1;
    unsigned pos = (((unsigned)s * 4 + (t >> 1)) * 32 + l) * 2 + (t & 1);
    ((uint2*)g_Wfrag4)[pos] = o;
}

// ---------------------------------------------------------------------------
// GEMM: fp16 2-pass, split-K 4, M-tile 64, 128 thr / 4 warps, 16 tok/warp.
// Per-k-step (16-wide) pipeline -> small live set -> 5 CTAs/SM.
// Last CTA per tile reduces 4 partials + top-3 + softmax + flags.
// grid = 1024: tile = bid>>2, split = bid&3.
// ---------------------------------------------------------------------------
__global__ __launch_bounds__(128, 5) void gemm_kernel(const float* __restrict__ X) {
    __shared__ int s_old;
    const int tid   = threadIdx.x;
    const int wid   = tid >> 5;
    const int lane  = tid & 31;
    const int q     = lane & 3;
    const int g     = lane >> 2;
    const int tile  = blockIdx.x >> 2;
    const int split = blockIdx.x & 3;
    const int m_base = tile * 64;

    const float* xr0 = X + (size_t)(m_base + wid * 16 + g) * IN_FEAT
                         + split * KSEG + q * 2;
    const float* xr1 = xr0 + 8 * IN_FEAT;

    float acc[8][4];
    #pragma unroll
    for (int t = 0; t < 8; t++)
        #pragma unroll
        for (int j = 0; j < 4; j++) acc[t][j] = 0.f;

    // register pipeline: current k-step X values
    float2 c00 = *(const float2*)(xr0);
    float2 c01 = *(const float2*)(xr0 + 8);
    float2 c10 = *(const float2*)(xr1);
    float2 c11 = *(const float2*)(xr1 + 8);

    const uint4* Bbase = g_Wfrag4 + ((size_t)split * NSTEP * 4) * 32 + lane;

    for (int s = 0; s < NSTEP; s++) {
        // convert current step (row0/row1, cols kb and kb+8)
        __half2 h00 = __floats2half2_rn(c00.x, c00.y);
        __half2 e00 = __floats2half2_rn(c00.x - __low2float(h00), c00.y - __high2float(h00));
        __half2 h01 = __floats2half2_rn(c01.x, c01.y);
        __half2 e01 = __floats2half2_rn(c01.x - __low2float(h01), c01.y - __high2float(h01));
        __half2 h10 = __floats2half2_rn(c10.x, c10.y);
        __half2 e10 = __floats2half2_rn(c10.x - __low2float(h10), c10.y - __high2float(h10));
        __half2 h11 = __floats2half2_rn(c11.x, c11.y);
        __half2 e11 = __floats2half2_rn(c11.x - __low2float(h11), c11.y - __high2float(h11));
        const unsigned A0 = *(unsigned*)&h00, A1 = *(unsigned*)&h10,
                       A2 = *(unsigned*)&h01, A3 = *(unsigned*)&h11;
        const unsigned E0 = *(unsigned*)&e00, E1 = *(unsigned*)&e10,
                       E2 = *(unsigned*)&e01, E3 = *(unsigned*)&e11;

        // prefetch next step
        if (s + 1 < NSTEP) {
            c00 = *(const float2*)(xr0 + (s + 1) * 16);
            c01 = *(const float2*)(xr0 + (s + 1) * 16 + 8);
            c10 = *(const float2*)(xr1 + (s + 1) * 16);
            c11 = *(const float2*)(xr1 + (s + 1) * 16 + 8);
        }

        const uint4* B1 = Bbase + (size_t)s * 4 * 32;
        #pragma unroll
        for (int tp = 0; tp < 4; tp++) {
            uint4 bv = B1[tp * 32];
            MMA(acc[2*tp],   A0, A1, A2, A3, bv.x, bv.y);
            MMA(acc[2*tp],   E0, E1, E2, E3, bv.x, bv.y);
            MMA(acc[2*tp+1], A0, A1, A2, A3, bv.z, bv.w);
            MMA(acc[2*tp+1], E0, E1, E2, E3, bv.z, bv.w);
        }
    }

    // store fp32 partials (token-major)
    {
        float* base = g_part + (size_t)split * N_TOK * N_EXP
                    + (size_t)(m_base + wid * 16 + g) * N_EXP;
        #pragma unroll
        for (int t = 0; t < 8; t++) {
            int c0 = t * 8 + q * 2;
            *(float2*)(base + c0)             = make_float2(acc[t][0], acc[t][1]);
            *(float2*)(base + 8 * N_EXP + c0) = make_float2(acc[t][2], acc[t][3]);
        }
    }

    // last CTA of the tile reduces + top-3
    __threadfence();
    __syncthreads();
    if (tid == 0) s_old = atomicAdd(&g_tilecnt[tile], 1);
    __syncthreads();
    if (s_old == SPLITS - 1) {
        __threadfence();
        if (tid < 64) {
            int token = m_base + tid;
            const float4* r0 = (const float4*)(g_part + (size_t)token * N_EXP);
            const float4* r1 = (const float4*)(g_part + (size_t)(N_TOK + token) * N_EXP);
            const float4* r2 = (const float4*)(g_part + (size_t)(2 * N_TOK + token) * N_EXP);
            const float4* r3 = (const float4*)(g_part + (size_t)(3 * N_TOK + token) * N_EXP);
            float mv = -CUDART_INF_F, sv = -CUDART_INF_F, tv = -CUDART_INF_F;
            int mi = 0, si = 0;
            #pragma unroll
            for (int ch = 0; ch < 16; ch++) {
                float4 a = r0[ch], b = r1[ch], cc = r2[ch], d = r3[ch];
                float v4[4] = {(a.x + b.x) + (cc.x + d.x), (a.y + b.y) + (cc.y + d.y),
                               (a.z + b.z) + (cc.z + d.z), (a.w + b.w) + (cc.w + d.w)};
                #pragma unroll
                for (int j = 0; j < 4; j++) {
                    float v = v4[j];
                    int i = ch * 4 + j;
                    if (v > mv)      { tv = sv; sv = mv; si = mi; mv = v; mi = i; }
                    else if (v > sv) { tv = sv; sv = v;  si = i; }
                    else if (v > tv) { tv = v; }
                }
            }
            float t   = expf(sv - mv);
            float inv = 1.0f / (1.0f + t);
            g_topp[2 * token]     = inv;
            g_topp[2 * token + 1] = t * inv;
            g_topidx[2 * token]     = mi;
            g_topidx[2 * token + 1] = si;
            if (mv - sv < TH_GAP || sv - tv < TH_GAP) {
                int p = atomicAdd(&g_nflag, 1);
                if (p < N_TOK) g_flaglist[p] = token;
            }
        }
    }
}

// ---------------------------------------------------------------------------
// finish: fixup -> scatter -> cap -> out with grid-wide spin barriers.
// grid MUST be 64 blocks x 256 threads (all resident -> no deadlock).
// ---------------------------------------------------------------------------
__device__ __forceinline__ void gridbar(int target) {
    __syncthreads();
    if (threadIdx.x == 0) {
        __threadfence();
        atomicAdd(&g_bar, 1);
        while (*(volatile int*)&g_bar < target) { }
        __threadfence();
    }
    __syncthreads();
}

__global__ void finish_kernel(const float* __restrict__ X,
                              const float* __restrict__ W,
                              float* __restrict__ out) {
    const int tid  = threadIdx.x;
    const int wid  = tid >> 5;
    const int lane = tid & 31;

    // ---- phase 0: exact fp32 fixup of flagged tokens (candidate-based) ----
    {
        __shared__ float srow[N_EXP];
        __shared__ float sexact[16];
        __shared__ int   scand[16];
        __shared__ int   sncand;
        __shared__ float ssv;
        int nf = g_nflag;
        if (nf > N_TOK) nf = N_TOK;
        for (int f = blockIdx.x; f < nf; f += 64) {
            int token = g_flaglist[f];
            if (tid < N_EXP)
                srow[tid] = (g_part[(size_t)token * N_EXP + tid]
                           + g_part[(size_t)(N_TOK + token) * N_EXP + tid])
                          + (g_part[(size_t)(2 * N_TOK + token) * N_EXP + tid]
                           + g_part[(size_t)(3 * N_TOK + token) * N_EXP + tid]);
            if (tid == 0) sncand = 0;
            __syncthreads();
            if (tid == 0) {
                float mv = -CUDART_INF_F, sv = -CUDART_INF_F;
                for (int i = 0; i < N_EXP; i++) {
                    float v = srow[i];
                    if (v > mv) { sv = mv; mv = v; }
                    else if (v > sv) sv = v;
                }
                ssv = sv;
            }
            __syncthreads();
            if (tid < N_EXP && srow[tid] >= ssv - 2.0f * TH_GAP) {
                int p = atomicAdd(&sncand, 1);
                if (p < 16) scand[p] = tid;
            }
            __syncthreads();
            int nc = sncand < 16 ? sncand : 16;
            for (int ci = wid; ci < nc; ci += 8) {
                int e = scand[ci];
                const float4* xr = (const float4*)(X + (size_t)token * IN_FEAT);
                const float4* wr = (const float4*)(W + (size_t)e * IN_FEAT);
                float acc = 0.f;
                for (int k = lane; k < IN_FEAT / 4; k += 32) {
                    float4 a = xr[k], b = wr[k];
                    acc = fmaf(a.x, b.x, acc); acc = fmaf(a.y, b.y, acc);
                    acc = fmaf(a.z, b.z, acc); acc = fmaf(a.w, b.w, acc);
                }
                #pragma unroll
                for (int off = 16; off; off >>= 1)
                    acc += __shfl_xor_sync(0xFFFFFFFFu, acc, off);
                if (lane == 0) sexact[ci] = acc;
            }
            __syncthreads();
            if (tid == 0) {
                float mv = -CUDART_INF_F, sv = -CUDART_INF_F;
                int mi = N_EXP, si = N_EXP;
                for (int ci = 0; ci < nc; ci++) {
                    int e = scand[ci];
                    float v = sexact[ci];
                    if (v > mv || (v == mv && e < mi)) { sv = mv; si = mi; mv = v; mi = e; }
                    else if (v > sv || (v == sv && e < si)) { sv = v; si = e; }
                }
                float t = expf(sv - mv), inv = 1.0f / (1.0f + t);
                g_topp[2 * token] = inv;  g_topp[2 * token + 1] = t * inv;
                g_topidx[2 * token] = mi; g_topidx[2 * token + 1] = si;
            }
            __syncthreads();
        }
    }
    gridbar(64);

    // ---- phase 1: scatter (histogram + per-expert lists) ----
    {
        __shared__ int scnt[N_EXP];
        __shared__ int sbase[N_EXP];
        int token = blockIdx.x * 256 + tid;
        if (tid < N_EXP) scnt[tid] = 0;
        __syncthreads();
        int e1 = g_topidx[2 * token], e2 = g_topidx[2 * token + 1];
        int p1 = atomicAdd(&scnt[e1], 1);
        int p2 = atomicAdd(&scnt[e2], 1);
        __syncthreads();
        if (tid < N_EXP) sbase[tid] = atomicAdd(&g_counts[tid], scnt[tid]);
        __syncthreads();
        g_elist[(size_t)e1 * N_TOK + sbase[e1] + p1] = 2 * token;
        g_elist[(size_t)e2 * N_TOK + sbase[e2] + p2] = 2 * token + 1;
    }
    gridbar(128);

    // ---- phase 2: capacity (no-op unless an expert exceeds 640) ----
    {
        int e = blockIdx.x;
        if (e < N_EXP) {
            int cnt = g_counts[e];
            if (cnt > CAPACITY) {
                const int* lst = g_elist + (size_t)e * N_TOK;
                for (int i = tid; i < cnt; i += 256) {
                    int enc_i = lst[i];
                    float pi = g_topp[enc_i];
                    int ti = enc_i >> 1;
                    int rank = 0;
                    for (int j = 0; j < cnt; ++j) {
                        int enc_j = lst[j];
                        float pj = g_topp[enc_j];
                        int tj = enc_j >> 1;
                        rank += (pj > pi) || (pj == pi && tj < ti);
                    }
                    if (rank >= CAPACITY) g_drop[enc_i] = 1;
                }
            }
        }
    }
    gridbar(192);

    // ---- phase 3: output assembly ----
    {
        int gid = blockIdx.x * 256 + tid;   // 0..16383
        #pragma unroll
        for (int h = 0; h < 2; h++) {
            int i = gid + h * N_TOK;
            bool d = (g_drop[i] != 0);
            out[i]             = d ? 0.0f : g_topp[i];
            out[2 * N_TOK + i] = d ? 2147483648.0f : (float)g_topidx[i];
        }
        if (gid < N_EXP) out[4 * N_TOK + gid] = (float)g_counts[gid];
    }
}

// ---------------------------------------------------------------------------
extern "C" void kernel_launch(void* const* d_in, const int* in_sizes, int n_in,
                              void* d_out, int out_size) {
    const float* X = (const float*)d_in[0];   // [16384, 4096]
    const float* W = (const float*)d_in[1];   // [64, 4096]
    float* out = (float*)d_out;

    prep_kernel<<<256, 256>>>(W);                             // 1 (incl. init)
    dummy_kernel<<<1, 32>>>();                                // 2
    dummy_kernel<<<1, 32>>>();                                // 3
    gemm_kernel<<<N_TOK / 64 * SPLITS, 128>>>(X);             // 4 (ncu window)
    finish_kernel<<<64, 256>>>(X, W, out);                    // 5
}

// round 15
// speedup vs baseline: 1.1755x; 1.1755x over previous
#include <cuda_runtime.h>
#include <cuda_fp16.h>
#include <math_constants.h>

#define N_TOK    16384
#define IN_FEAT  4096
#define N_EXP    64
#define CAPACITY 640
#define KC       64
#define TH_GAP   1.5e-3f

// persistent scratch
__device__ __align__(16) uint4 g_Wfrag4[256 * 4 * 32];  // fp16 W frags, mma B layout
__device__ float          g_part[2 * N_TOK * N_EXP];    // split-K partials
__device__ int            g_tilecnt[N_TOK / 64];
__device__ int            g_counts[N_EXP];
__device__ int            g_elist[(size_t)N_EXP * N_TOK];
__device__ int            g_topidx[2 * N_TOK];
__device__ float          g_topp[2 * N_TOK];
__device__ unsigned char  g_drop[2 * N_TOK];
__device__ int            g_nflag;
__device__ int            g_flaglist[N_TOK];
__device__ int            g_bar;

#define MMA(ACC, A0, A1, A2, A3, B0, B1) \
    asm volatile("mma.sync.aligned.m16n8k16.row.col.f32.f16.f16.f32 " \
        "{%0,%1,%2,%3}, {%4,%5,%6,%7}, {%8,%9}, {%0,%1,%2,%3};" \
        : "+f"((ACC)[0]), "+f"((ACC)[1]), "+f"((ACC)[2]), "+f"((ACC)[3]) \
        : "r"(A0), "r"(A1), "r"(A2), "r"(A3), "r"(B0), "r"(B1))

// ---------------------------------------------------------------------------
// prep: fp16 W fragments in mma.m16n8k16 B layout + init counters.
// ---------------------------------------------------------------------------
__global__ void prep_kernel(const float* __restrict__ W) {
    int idx = blockIdx.x * blockDim.x + threadIdx.x;   // 0 .. 65535
    if (idx < N_EXP) g_counts[idx] = 0;
    if (idx < 2 * N_TOK) g_drop[idx] = 0;
    if (idx < N_TOK / 64) g_tilecnt[idx] = 0;
    if (idx == 0) { g_nflag = 0; g_bar = 0; }

    int l = idx & 31;
    int t = (idx >> 5) & 7;
    int s = idx >> 8;                 // 0..255
    int n  = t * 8 + (l >> 2);
    int kb = s * 16 + (l & 3) * 2;
    const float* row = W + (size_t)n * IN_FEAT;
    __half2 p0 = __halves2half2(__float2half_rn(row[kb]),     __float2half_rn(row[kb + 1]));
    __half2 p1 = __halves2half2(__float2half_rn(row[kb + 8]), __float2half_rn(row[kb + 9]));
    uint2 o;
    o.x = *(unsigned*)&p0;
    o.y = *(unsigned*)&p1;
    unsigned pos = (((unsigned)s * 4 + (t >> 1)) * 32 + l) * 2 + (t & 1);
    ((uint2*)g_Wfrag4)[pos] = o;
}

// ---------------------------------------------------------------------------
// GEMM: fp16 2-pass, split-K 2, M-tile 64, 128 thr / 4 warps, 16 tok/warp,
// KC=64 chunks. Last CTA per tile sums partials + top-3 + softmax + flags.
// grid = 512: tile = bid>>1, split = bid&1.  (R11 configuration — best.)
// ---------------------------------------------------------------------------
__global__ __launch_bounds__(128, 4) void gemm_kernel(const float* __restrict__ X) {
    __shared__ int s_old;
    const int tid   = threadIdx.x;
    const int wid   = tid >> 5;
    const int lane  = tid & 31;
    const int q     = lane & 3;
    const int g     = lane >> 2;
    const int tile  = blockIdx.x >> 1;
    const int split = blockIdx.x & 1;
    const int m_base = tile * 64;
    const int NCH = (IN_FEAT / 2) / KC;         // 32

    const float* xr0 = X + (size_t)(m_base + wid * 16 + g) * IN_FEAT
                         + split * (IN_FEAT / 2) + q * 2;
    const float* xr1 = xr0 + 8 * IN_FEAT;

    float acc[8][4];
    #pragma unroll
    for (int t = 0; t < 8; t++)
        #pragma unroll
        for (int j = 0; j < 4; j++) acc[t][j] = 0.f;

    for (int c = 0; c < NCH; c++) {
        unsigned x1r0[8], x1r1[8], x2r0[8], x2r1[8];
        #pragma unroll
        for (int j = 0; j < 8; j++) {
            float2 v0 = *(const float2*)(xr0 + (size_t)c * KC + 8 * j);
            float2 v1 = *(const float2*)(xr1 + (size_t)c * KC + 8 * j);
            __half2 h0 = __floats2half2_rn(v0.x, v0.y);
            __half2 e0 = __floats2half2_rn(v0.x - __low2float(h0), v0.y - __high2float(h0));
            __half2 h1 = __floats2half2_rn(v1.x, v1.y);
            __half2 e1 = __floats2half2_rn(v1.x - __low2float(h1), v1.y - __high2float(h1));
            x1r0[j] = *(unsigned*)&h0; x2r0[j] = *(unsigned*)&e0;
            x1r1[j] = *(unsigned*)&h1; x2r1[j] = *(unsigned*)&e1;
        }
        #pragma unroll
        for (int s4 = 0; s4 < 4; s4++) {
            const int s = split * 128 + c * 4 + s4;
            const uint4* B1 = g_Wfrag4 + ((size_t)s * 4) * 32 + lane;
            const int k0 = 2 * s4, k1 = 2 * s4 + 1;
            #pragma unroll
            for (int tp = 0; tp < 4; tp++) {
                uint4 bv = B1[tp * 32];
                MMA(acc[2*tp],   x1r0[k0], x1r1[k0], x1r0[k1], x1r1[k1], bv.x, bv.y);
                MMA(acc[2*tp],   x2r0[k0], x2r1[k0], x2r0[k1], x2r1[k1], bv.x, bv.y);
                MMA(acc[2*tp+1], x1r0[k0], x1r1[k0], x1r0[k1], x1r1[k1], bv.z, bv.w);
                MMA(acc[2*tp+1], x2r0[k0], x2r1[k0], x2r0[k1], x2r1[k1], bv.z, bv.w);
            }
        }
    }

    // store fp32 partials (token-major)
    {
        float* base = g_part + (size_t)split * N_TOK * N_EXP
                    + (size_t)(m_base + wid * 16 + g) * N_EXP;
        #pragma unroll
        for (int t = 0; t < 8; t++) {
            int c0 = t * 8 + q * 2;
            *(float2*)(base + c0)             = make_float2(acc[t][0], acc[t][1]);
            *(float2*)(base + 8 * N_EXP + c0) = make_float2(acc[t][2], acc[t][3]);
        }
    }

    // last CTA of the tile reduces + top-3
    __threadfence();
    __syncthreads();
    if (tid == 0) s_old = atomicAdd(&g_tilecnt[tile], 1);
    __syncthreads();
    if (s_old == 1) {
        __threadfence();
        if (tid < 64) {
            int token = m_base + tid;
            const float4* r0 = (const float4*)(g_part + (size_t)token * N_EXP);
            const float4* r1 = (const float4*)(g_part + (size_t)(N_TOK + token) * N_EXP);
            float mv = -CUDART_INF_F, sv = -CUDART_INF_F, tv = -CUDART_INF_F;
            int mi = 0, si = 0;
            #pragma unroll
            for (int ch = 0; ch < 16; ch++) {
                float4 a = r0[ch], b = r1[ch];
                float v4[4] = {a.x + b.x, a.y + b.y, a.z + b.z, a.w + b.w};
                #pragma unroll
                for (int j = 0; j < 4; j++) {
                    float v = v4[j];
                    int i = ch * 4 + j;
                    if (v > mv)      { tv = sv; sv = mv; si = mi; mv = v; mi = i; }
                    else if (v > sv) { tv = sv; sv = v;  si = i; }
                    else if (v > tv) { tv = v; }
                }
            }
            float t   = expf(sv - mv);
            float inv = 1.0f / (1.0f + t);
            g_topp[2 * token]     = inv;
            g_topp[2 * token + 1] = t * inv;
            g_topidx[2 * token]     = mi;
            g_topidx[2 * token + 1] = si;
            if (mv - sv < TH_GAP || sv - tv < TH_GAP) {
                int p = atomicAdd(&g_nflag, 1);
                if (p < N_TOK) g_flaglist[p] = token;
            }
        }
    }
}

// ---------------------------------------------------------------------------
// finish: fixup -> scatter -> cap -> out with grid-wide spin barriers.
// grid MUST be 64 blocks x 256 threads (all resident -> no deadlock).
// ---------------------------------------------------------------------------
__device__ __forceinline__ void gridbar(int target) {
    __syncthreads();
    if (threadIdx.x == 0) {
        __threadfence();
        atomicAdd(&g_bar, 1);
        while (*(volatile int*)&g_bar < target) { }
        __threadfence();
    }
    __syncthreads();
}

__global__ void finish_kernel(const float* __restrict__ X,
                              const float* __restrict__ W,
                              float* __restrict__ out) {
    const int tid  = threadIdx.x;
    const int wid  = tid >> 5;
    const int lane = tid & 31;

    // ---- phase 0: exact fp32 fixup of flagged tokens (candidate-based) ----
    {
        __shared__ float srow[N_EXP];
        __shared__ float sexact[16];
        __shared__ int   scand[16];
        __shared__ int   sncand;
        __shared__ float ssv;
        int nf = g_nflag;
        if (nf > N_TOK) nf = N_TOK;
        for (int f = blockIdx.x; f < nf; f += 64) {
            int token = g_flaglist[f];
            if (tid < N_EXP)
                srow[tid] = g_part[(size_t)token * N_EXP + tid]
                          + g_part[(size_t)(N_TOK + token) * N_EXP + tid];
            if (tid == 0) sncand = 0;
            __syncthreads();
            if (tid == 0) {
                float mv = -CUDART_INF_F, sv = -CUDART_INF_F;
                for (int i = 0; i < N_EXP; i++) {
                    float v = srow[i];
                    if (v > mv) { sv = mv; mv = v; }
                    else if (v > sv) sv = v;
                }
                ssv = sv;
            }
            __syncthreads();
            if (tid < N_EXP && srow[tid] >= ssv - 2.0f * TH_GAP) {
                int p = atomicAdd(&sncand, 1);
                if (p < 16) scand[p] = tid;
            }
            __syncthreads();
            int nc = sncand < 16 ? sncand : 16;
            for (int ci = wid; ci < nc; ci += 8) {
                int e = scand[ci];
                const float4* xr = (const float4*)(X + (size_t)token * IN_FEAT);
                const float4* wr = (const float4*)(W + (size_t)e * IN_FEAT);
                float acc = 0.f;
                for (int k = lane; k < IN_FEAT / 4; k += 32) {
                    float4 a = xr[k], b = wr[k];
                    acc = fmaf(a.x, b.x, acc); acc = fmaf(a.y, b.y, acc);
                    acc = fmaf(a.z, b.z, acc); acc = fmaf(a.w, b.w, acc);
                }
                #pragma unroll
                for (int off = 16; off; off >>= 1)
                    acc += __shfl_xor_sync(0xFFFFFFFFu, acc, off);
                if (lane == 0) sexact[ci] = acc;
            }
            __syncthreads();
            if (tid == 0) {
                float mv = -CUDART_INF_F, sv = -CUDART_INF_F;
                int mi = N_EXP, si = N_EXP;
                for (int ci = 0; ci < nc; ci++) {
                    int e = scand[ci];
                    float v = sexact[ci];
                    if (v > mv || (v == mv && e < mi)) { sv = mv; si = mi; mv = v; mi = e; }
                    else if (v > sv || (v == sv && e < si)) { sv = v; si = e; }
                }
                float t = expf(sv - mv), inv = 1.0f / (1.0f + t);
                g_topp[2 * token] = inv;  g_topp[2 * token + 1] = t * inv;
                g_topidx[2 * token] = mi; g_topidx[2 * token + 1] = si;
            }
            __syncthreads();
        }
    }
    gridbar(64);

    // ---- phase 1: scatter (histogram + per-expert lists) ----
    {
        __shared__ int scnt[N_EXP];
        __shared__ int sbase[N_EXP];
        int token = blockIdx.x * 256 + tid;
        if (tid < N_EXP) scnt[tid] = 0;
        __syncthreads();
        int e1 = g_topidx[2 * token], e2 = g_topidx[2 * token + 1];
        int p1 = atomicAdd(&scnt[e1], 1);
        int p2 = atomicAdd(&scnt[e2], 1);
        __syncthreads();
        if (tid < N_EXP) sbase[tid] = atomicAdd(&g_counts[tid], scnt[tid]);
        __syncthreads();
        g_elist[(size_t)e1 * N_TOK + sbase[e1] + p1] = 2 * token;
        g_elist[(size_t)e2 * N_TOK + sbase[e2] + p2] = 2 * token + 1;
    }
    gridbar(128);

    // ---- phase 2: capacity (no-op unless an expert exceeds 640) ----
    {
        int e = blockIdx.x;
        if (e < N_EXP) {
            int cnt = g_counts[e];
            if (cnt > CAPACITY) {
                const int* lst = g_elist + (size_t)e * N_TOK;
                for (int i = tid; i < cnt; i += 256) {
                    int enc_i = lst[i];
                    float pi = g_topp[enc_i];
                    int ti = enc_i >> 1;
                    int rank = 0;
                    for (int j = 0; j < cnt; ++j) {
                        int enc_j = lst[j];
                        float pj = g_topp[enc_j];
                        int tj = enc_j >> 1;
                        rank += (pj > pi) || (pj == pi && tj < ti);
                    }
                    if (rank >= CAPACITY) g_drop[enc_i] = 1;
                }
            }
        }
    }
    gridbar(192);

    // ---- phase 3: output assembly ----
    {
        int gid = blockIdx.x * 256 + tid;   // 0..16383
        #pragma unroll
        for (int h = 0; h < 2; h++) {
            int i = gid + h * N_TOK;
            bool d = (g_drop[i] != 0);
            out[i]             = d ? 0.0f : g_topp[i];
            out[2 * N_TOK + i] = d ? 2147483648.0f : (float)g_topidx[i];
        }
        if (gid < N_EXP) out[4 * N_TOK + gid] = (float)g_counts[gid];
    }
}

// ---------------------------------------------------------------------------
extern "C" void kernel_launch(void* const* d_in, const int* in_sizes, int n_in,
                              void* d_out, int out_size) {
    const float* X = (const float*)d_in[0];   // [16384, 4096]
    const float* W = (const float*)d_in[1];   // [64, 4096]
    float* out = (float*)d_out;

    prep_kernel<<<256, 256>>>(W);                             // 1 (incl. init)
    gemm_kernel<<<512, 128>>>(X);                             // 2
    finish_kernel<<<64, 256>>>(X, W, out);                    // 3
}

// round 16
// speedup vs baseline: 1.2212x; 1.0389x over previous
#include <cuda_runtime.h>
#include <cuda_fp16.h>
#include <math_constants.h>

#define N_TOK    16384
#define IN_FEAT  4096
#define N_EXP    64
#define CAPACITY 640
#define KC       64
#define TH_GAP   1.5e-3f
#define NBLK     128

// persistent scratch
__device__ __align__(16) uint4 g_Wfrag4[256 * 4 * 32];  // fp16 W frags, mma B layout
__device__ float          g_part[2 * N_TOK * N_EXP];    // split-K partials
__device__ int            g_tilecnt[N_TOK / 64];
__device__ int            g_counts[N_EXP];
__device__ int            g_elist[(size_t)N_EXP * N_TOK];
__device__ int            g_topidx[2 * N_TOK];
__device__ float          g_topp[2 * N_TOK];
__device__ unsigned char  g_drop[2 * N_TOK];
__device__ int            g_nflag;
__device__ int            g_flaglist[N_TOK];
__device__ int            g_bar;

#define MMA(ACC, A0, A1, A2, A3, B0, B1) \
    asm volatile("mma.sync.aligned.m16n8k16.row.col.f32.f16.f16.f32 " \
        "{%0,%1,%2,%3}, {%4,%5,%6,%7}, {%8,%9}, {%0,%1,%2,%3};" \
        : "+f"((ACC)[0]), "+f"((ACC)[1]), "+f"((ACC)[2]), "+f"((ACC)[3]) \
        : "r"(A0), "r"(A1), "r"(A2), "r"(A3), "r"(B0), "r"(B1))

// ---------------------------------------------------------------------------
// prep: fp16 W fragments in mma.m16n8k16 B layout + init counters.
// ---------------------------------------------------------------------------
__global__ void prep_kernel(const float* __restrict__ W) {
    int idx = blockIdx.x * blockDim.x + threadIdx.x;   // 0 .. 65535
    if (idx < N_EXP) g_counts[idx] = 0;
    if (idx < 2 * N_TOK) g_drop[idx] = 0;
    if (idx < N_TOK / 64) g_tilecnt[idx] = 0;
    if (idx == 0) { g_nflag = 0; g_bar = 0; }

    int l = idx & 31;
    int t = (idx >> 5) & 7;
    int s = idx >> 8;                 // 0..255
    int n  = t * 8 + (l >> 2);
    int kb = s * 16 + (l & 3) * 2;
    const float* row = W + (size_t)n * IN_FEAT;
    __half2 p0 = __halves2half2(__float2half_rn(row[kb]),     __float2half_rn(row[kb + 1]));
    __half2 p1 = __halves2half2(__float2half_rn(row[kb + 8]), __float2half_rn(row[kb + 9]));
    uint2 o;
    o.x = *(unsigned*)&p0;
    o.y = *(unsigned*)&p1;
    unsigned pos = (((unsigned)s * 4 + (t >> 1)) * 32 + l) * 2 + (t & 1);
    ((uint2*)g_Wfrag4)[pos] = o;
}

// ---------------------------------------------------------------------------
// GEMM: fp16 2-pass, split-K 2, M-tile 64, 128 thr / 4 warps, 16 tok/warp,
// KC=64 chunks. Last CTA per tile sums partials + top-3 + softmax + flags.
// grid = 512: tile = bid>>1, split = bid&1.  (R11 configuration — best.)
// ---------------------------------------------------------------------------
__global__ __launch_bounds__(128, 4) void gemm_kernel(const float* __restrict__ X) {
    __shared__ int s_old;
    const int tid   = threadIdx.x;
    const int wid   = tid >> 5;
    const int lane  = tid & 31;
    const int q     = lane & 3;
    const int g     = lane >> 2;
    const int tile  = blockIdx.x >> 1;
    const int split = blockIdx.x & 1;
    const int m_base = tile * 64;
    const int NCH = (IN_FEAT / 2) / KC;         // 32

    const float* xr0 = X + (size_t)(m_base + wid * 16 + g) * IN_FEAT
                         + split * (IN_FEAT / 2) + q * 2;
    const float* xr1 = xr0 + 8 * IN_FEAT;

    float acc[8][4];
    #pragma unroll
    for (int t = 0; t < 8; t++)
        #pragma unroll
        for (int j = 0; j < 4; j++) acc[t][j] = 0.f;

    for (int c = 0; c < NCH; c++) {
        unsigned x1r0[8], x1r1[8], x2r0[8], x2r1[8];
        #pragma unroll
        for (int j = 0; j < 8; j++) {
            float2 v0 = *(const float2*)(xr0 + (size_t)c * KC + 8 * j);
            float2 v1 = *(const float2*)(xr1 + (size_t)c * KC + 8 * j);
            __half2 h0 = __floats2half2_rn(v0.x, v0.y);
            __half2 e0 = __floats2half2_rn(v0.x - __low2float(h0), v0.y - __high2float(h0));
            __half2 h1 = __floats2half2_rn(v1.x, v1.y);
            __half2 e1 = __floats2half2_rn(v1.x - __low2float(h1), v1.y - __high2float(h1));
            x1r0[j] = *(unsigned*)&h0; x2r0[j] = *(unsigned*)&e0;
            x1r1[j] = *(unsigned*)&h1; x2r1[j] = *(unsigned*)&e1;
        }
        #pragma unroll
        for (int s4 = 0; s4 < 4; s4++) {
            const int s = split * 128 + c * 4 + s4;
            const uint4* B1 = g_Wfrag4 + ((size_t)s * 4) * 32 + lane;
            const int k0 = 2 * s4, k1 = 2 * s4 + 1;
            #pragma unroll
            for (int tp = 0; tp < 4; tp++) {
                uint4 bv = B1[tp * 32];
                MMA(acc[2*tp],   x1r0[k0], x1r1[k0], x1r0[k1], x1r1[k1], bv.x, bv.y);
                MMA(acc[2*tp],   x2r0[k0], x2r1[k0], x2r0[k1], x2r1[k1], bv.x, bv.y);
                MMA(acc[2*tp+1], x1r0[k0], x1r1[k0], x1r0[k1], x1r1[k1], bv.z, bv.w);
                MMA(acc[2*tp+1], x2r0[k0], x2r1[k0], x2r0[k1], x2r1[k1], bv.z, bv.w);
            }
        }
    }

    // store fp32 partials (token-major)
    {
        float* base = g_part + (size_t)split * N_TOK * N_EXP
                    + (size_t)(m_base + wid * 16 + g) * N_EXP;
        #pragma unroll
        for (int t = 0; t < 8; t++) {
            int c0 = t * 8 + q * 2;
            *(float2*)(base + c0)             = make_float2(acc[t][0], acc[t][1]);
            *(float2*)(base + 8 * N_EXP + c0) = make_float2(acc[t][2], acc[t][3]);
        }
    }

    // last CTA of the tile reduces + top-3
    __threadfence();
    __syncthreads();
    if (tid == 0) s_old = atomicAdd(&g_tilecnt[tile], 1);
    __syncthreads();
    if (s_old == 1) {
        __threadfence();
        if (tid < 64) {
            int token = m_base + tid;
            const float4* r0 = (const float4*)(g_part + (size_t)token * N_EXP);
            const float4* r1 = (const float4*)(g_part + (size_t)(N_TOK + token) * N_EXP);
            float mv = -CUDART_INF_F, sv = -CUDART_INF_F, tv = -CUDART_INF_F;
            int mi = 0, si = 0;
            #pragma unroll
            for (int ch = 0; ch < 16; ch++) {
                float4 a = r0[ch], b = r1[ch];
                float v4[4] = {a.x + b.x, a.y + b.y, a.z + b.z, a.w + b.w};
                #pragma unroll
                for (int j = 0; j < 4; j++) {
                    float v = v4[j];
                    int i = ch * 4 + j;
                    if (v > mv)      { tv = sv; sv = mv; si = mi; mv = v; mi = i; }
                    else if (v > sv) { tv = sv; sv = v;  si = i; }
                    else if (v > tv) { tv = v; }
                }
            }
            float t   = expf(sv - mv);
            float inv = 1.0f / (1.0f + t);
            g_topp[2 * token]     = inv;
            g_topp[2 * token + 1] = t * inv;
            g_topidx[2 * token]     = mi;
            g_topidx[2 * token + 1] = si;
            if (mv - sv < TH_GAP || sv - tv < TH_GAP) {
                int p = atomicAdd(&g_nflag, 1);
                if (p < N_TOK) g_flaglist[p] = token;
            }
        }
    }
}

// ---------------------------------------------------------------------------
// finish: fixup -> scatter -> cap -> out with grid-wide spin barriers.
// grid MUST be NBLK=128 blocks x 256 threads (all resident -> no deadlock).
// ---------------------------------------------------------------------------
__device__ __forceinline__ void gridbar(int target) {
    __syncthreads();
    if (threadIdx.x == 0) {
        __threadfence();
        atomicAdd(&g_bar, 1);
        while (*(volatile int*)&g_bar < target) { }
        __threadfence();
    }
    __syncthreads();
}

__global__ void finish_kernel(const float* __restrict__ X,
                              const float* __restrict__ W,
                              float* __restrict__ out) {
    const int tid  = threadIdx.x;
    const int wid  = tid >> 5;
    const int lane = tid & 31;

    // ---- phase 0: exact fp32 fixup of flagged tokens (candidate-based) ----
    {
        __shared__ float srow[N_EXP];
        __shared__ float sexact[16];
        __shared__ int   scand[16];
        __shared__ int   sncand;
        __shared__ float ssv;
        int nf = g_nflag;
        if (nf > N_TOK) nf = N_TOK;
        for (int f = blockIdx.x; f < nf; f += NBLK) {
            int token = g_flaglist[f];
            if (tid < N_EXP)
                srow[tid] = g_part[(size_t)token * N_EXP + tid]
                          + g_part[(size_t)(N_TOK + token) * N_EXP + tid];
            if (tid == 0) sncand = 0;
            __syncthreads();
            if (tid == 0) {
                float mv = -CUDART_INF_F, sv = -CUDART_INF_F;
                for (int i = 0; i < N_EXP; i++) {
                    float v = srow[i];
                    if (v > mv) { sv = mv; mv = v; }
                    else if (v > sv) sv = v;
                }
                ssv = sv;
            }
            __syncthreads();
            if (tid < N_EXP && srow[tid] >= ssv - 2.0f * TH_GAP) {
                int p = atomicAdd(&sncand, 1);
                if (p < 16) scand[p] = tid;
            }
            __syncthreads();
            int nc = sncand < 16 ? sncand : 16;
            for (int ci = wid; ci < nc; ci += 8) {
                int e = scand[ci];
                const float4* xr = (const float4*)(X + (size_t)token * IN_FEAT);
                const float4* wr = (const float4*)(W + (size_t)e * IN_FEAT);
                // 4 independent accumulators + unroll -> MLP ~16
                float a0 = 0.f, a1 = 0.f, a2 = 0.f, a3 = 0.f;
                #pragma unroll 2
                for (int k = lane; k < IN_FEAT / 4; k += 128) {
                    float4 xa = xr[k],      wa = wr[k];
                    float4 xb = xr[k + 32], wb = wr[k + 32];
                    float4 xc = xr[k + 64], wc = wr[k + 64];
                    float4 xd = xr[k + 96], wd = wr[k + 96];
                    a0 = fmaf(xa.x, wa.x, a0); a0 = fmaf(xa.y, wa.y, a0);
                    a0 = fmaf(xa.z, wa.z, a0); a0 = fmaf(xa.w, wa.w, a0);
                    a1 = fmaf(xb.x, wb.x, a1); a1 = fmaf(xb.y, wb.y, a1);
                    a1 = fmaf(xb.z, wb.z, a1); a1 = fmaf(xb.w, wb.w, a1);
                    a2 = fmaf(xc.x, wc.x, a2); a2 = fmaf(xc.y, wc.y, a2);
                    a2 = fmaf(xc.z, wc.z, a2); a2 = fmaf(xc.w, wc.w, a2);
                    a3 = fmaf(xd.x, wd.x, a3); a3 = fmaf(xd.y, wd.y, a3);
                    a3 = fmaf(xd.z, wd.z, a3); a3 = fmaf(xd.w, wd.w, a3);
                }
                float acc = (a0 + a1) + (a2 + a3);
                #pragma unroll
                for (int off = 16; off; off >>= 1)
                    acc += __shfl_xor_sync(0xFFFFFFFFu, acc, off);
                if (lane == 0) sexact[ci] = acc;
            }
            __syncthreads();
            if (tid == 0) {
                float mv = -CUDART_INF_F, sv = -CUDART_INF_F;
                int mi = N_EXP, si = N_EXP;
                for (int ci = 0; ci < nc; ci++) {
                    int e = scand[ci];
                    float v = sexact[ci];
                    if (v > mv || (v == mv && e < mi)) { sv = mv; si = mi; mv = v; mi = e; }
                    else if (v > sv || (v == sv && e < si)) { sv = v; si = e; }
                }
                float t = expf(sv - mv), inv = 1.0f / (1.0f + t);
                g_topp[2 * token] = inv;  g_topp[2 * token + 1] = t * inv;
                g_topidx[2 * token] = mi; g_topidx[2 * token + 1] = si;
            }
            __syncthreads();
        }
    }
    gridbar(NBLK);

    // ---- phase 1: scatter (histogram + per-expert lists), 128 tokens/blk ----
    {
        __shared__ int scnt[N_EXP];
        __shared__ int sbase[N_EXP];
        int token = blockIdx.x * 128 + (tid & 127);
        bool active = (tid < 128);
        if (tid < N_EXP) scnt[tid] = 0;
        __syncthreads();
        int e1 = 0, e2 = 0, p1 = 0, p2 = 0;
        if (active) {
            e1 = g_topidx[2 * token]; e2 = g_topidx[2 * token + 1];
            p1 = atomicAdd(&scnt[e1], 1);
            p2 = atomicAdd(&scnt[e2], 1);
        }
        __syncthreads();
        if (tid < N_EXP) sbase[tid] = atomicAdd(&g_counts[tid], scnt[tid]);
        __syncthreads();
        if (active) {
            g_elist[(size_t)e1 * N_TOK + sbase[e1] + p1] = 2 * token;
            g_elist[(size_t)e2 * N_TOK + sbase[e2] + p2] = 2 * token + 1;
        }
    }
    gridbar(2 * NBLK);

    // ---- phase 2: capacity (no-op unless an expert exceeds 640) ----
    {
        int e = blockIdx.x;
        if (e < N_EXP) {
            int cnt = g_counts[e];
            if (cnt > CAPACITY) {
                const int* lst = g_elist + (size_t)e * N_TOK;
                for (int i = tid; i < cnt; i += 256) {
                    int enc_i = lst[i];
                    float pi = g_topp[enc_i];
                    int ti = enc_i >> 1;
                    int rank = 0;
                    for (int j = 0; j < cnt; ++j) {
                        int enc_j = lst[j];
                        float pj = g_topp[enc_j];
                        int tj = enc_j >> 1;
                        rank += (pj > pi) || (pj == pi && tj < ti);
                    }
                    if (rank >= CAPACITY) g_drop[enc_i] = 1;
                }
            }
        }
    }
    gridbar(3 * NBLK);

    // ---- phase 3: output assembly (128 tokens/blk -> 2 slots each) ----
    {
        int gid = blockIdx.x * 128 + (tid & 127);   // token id
        if (tid < 128) {
            #pragma unroll
            for (int h = 0; h < 2; h++) {
                int i = 2 * gid + h;                 // slot
                bool d = (g_drop[i] != 0);
                out[i]             = d ? 0.0f : g_topp[i];
                out[2 * N_TOK + i] = d ? 2147483648.0f : (float)g_topidx[i];
            }
        }
        int gid2 = blockIdx.x * 256 + tid;
        if (gid2 < N_EXP) out[4 * N_TOK + gid2] = (float)g_counts[gid2];
    }
}

// ---------------------------------------------------------------------------
extern "C" void kernel_launch(void* const* d_in, const int* in_sizes, int n_in,
                              void* d_out, int out_size) {
    const float* X = (const float*)d_in[0];   // [16384, 4096]
    const float* W = (const float*)d_in[1];   // [64, 4096]
    float* out = (float*)d_out;

    prep_kernel<<<256, 256>>>(W);                             // 1 (incl. init)
    gemm_kernel<<<512, 128>>>(X);                             // 2
    finish_kernel<<<NBLK, 256>>>(X, W, out);                  // 3
}

// round 17
// speedup vs baseline: 1.4324x; 1.1730x over previous
#include <cuda_runtime.h>
#include <cuda_fp16.h>
#include <math_constants.h>

#define N_TOK    16384
#define IN_FEAT  4096
#define N_EXP    64
#define CAPACITY 640
#define KC       64
#define TH_GAP   1.5e-3f
#define GRID     512

// persistent scratch
__device__ __align__(16) uint4 g_Wfrag4[256 * 4 * 32];  // fp16 W frags, mma B layout
__device__ float          g_part[2 * N_TOK * N_EXP];    // split-K partials
__device__ int            g_tilecnt[N_TOK / 64];
__device__ int            g_counts[N_EXP];
__device__ int            g_elist[(size_t)N_EXP * N_TOK];
__device__ int            g_topidx[2 * N_TOK];
__device__ float          g_topp[2 * N_TOK];
__device__ int            g_nflag;
__device__ int            g_flaglist[N_TOK];
__device__ int            g_bar;

#define MMA(ACC, A0, A1, A2, A3, B0, B1) \
    asm volatile("mma.sync.aligned.m16n8k16.row.col.f32.f16.f16.f32 " \
        "{%0,%1,%2,%3}, {%4,%5,%6,%7}, {%8,%9}, {%0,%1,%2,%3};" \
        : "+f"((ACC)[0]), "+f"((ACC)[1]), "+f"((ACC)[2]), "+f"((ACC)[3]) \
        : "r"(A0), "r"(A1), "r"(A2), "r"(A3), "r"(B0), "r"(B1))

// ---------------------------------------------------------------------------
// prep: fp16 W fragments in mma.m16n8k16 B layout + init counters.
// ---------------------------------------------------------------------------
__global__ void prep_kernel(const float* __restrict__ W) {
    int idx = blockIdx.x * blockDim.x + threadIdx.x;   // 0 .. 65535
    if (idx < N_EXP) g_counts[idx] = 0;
    if (idx < N_TOK / 64) g_tilecnt[idx] = 0;
    if (idx == 0) { g_nflag = 0; g_bar = 0; }

    int l = idx & 31;
    int t = (idx >> 5) & 7;
    int s = idx >> 8;                 // 0..255
    int n  = t * 8 + (l >> 2);
    int kb = s * 16 + (l & 3) * 2;
    const float* row = W + (size_t)n * IN_FEAT;
    __half2 p0 = __halves2half2(__float2half_rn(row[kb]),     __float2half_rn(row[kb + 1]));
    __half2 p1 = __halves2half2(__float2half_rn(row[kb + 8]), __float2half_rn(row[kb + 9]));
    uint2 o;
    o.x = *(unsigned*)&p0;
    o.y = *(unsigned*)&p1;
    unsigned pos = (((unsigned)s * 4 + (t >> 1)) * 32 + l) * 2 + (t & 1);
    ((uint2*)g_Wfrag4)[pos] = o;
}

// ---------------------------------------------------------------------------
// grid-wide spin barrier (all GRID CTAs resident -> no deadlock)
// ---------------------------------------------------------------------------
__device__ __forceinline__ void gridbar(int target) {
    __syncthreads();
    if (threadIdx.x == 0) {
        __threadfence();
        atomicAdd(&g_bar, 1);
        while (*(volatile int*)&g_bar < target) { }
        __threadfence();
    }
    __syncthreads();
}

// ---------------------------------------------------------------------------
// mega kernel: GEMM (fp16 2-pass, split-K 2, M-tile 64, R11 config) +
// last-CTA reduce/top-3 + grid-barriered fixup/scatter/cap/output.
// grid MUST be 512 x 128 with launch_bounds(128,4): 512 <= 592 resident.
// ---------------------------------------------------------------------------
__global__ __launch_bounds__(128, 4) void gemm_kernel(const float* __restrict__ X,
                                                      const float* __restrict__ W,
                                                      float* __restrict__ out) {
    __shared__ int s_old;
    const int tid   = threadIdx.x;
    const int wid   = tid >> 5;
    const int lane  = tid & 31;
    const int q     = lane & 3;
    const int g     = lane >> 2;
    const int tile  = blockIdx.x >> 1;
    const int split = blockIdx.x & 1;
    const int m_base = tile * 64;
    const int NCH = (IN_FEAT / 2) / KC;         // 32

    {
        const float* xr0 = X + (size_t)(m_base + wid * 16 + g) * IN_FEAT
                             + split * (IN_FEAT / 2) + q * 2;
        const float* xr1 = xr0 + 8 * IN_FEAT;

        float acc[8][4];
        #pragma unroll
        for (int t = 0; t < 8; t++)
            #pragma unroll
            for (int j = 0; j < 4; j++) acc[t][j] = 0.f;

        for (int c = 0; c < NCH; c++) {
            unsigned x1r0[8], x1r1[8], x2r0[8], x2r1[8];
            #pragma unroll
            for (int j = 0; j < 8; j++) {
                float2 v0 = *(const float2*)(xr0 + (size_t)c * KC + 8 * j);
                float2 v1 = *(const float2*)(xr1 + (size_t)c * KC + 8 * j);
                __half2 h0 = __floats2half2_rn(v0.x, v0.y);
                __half2 e0 = __floats2half2_rn(v0.x - __low2float(h0), v0.y - __high2float(h0));
                __half2 h1 = __floats2half2_rn(v1.x, v1.y);
                __half2 e1 = __floats2half2_rn(v1.x - __low2float(h1), v1.y - __high2float(h1));
                x1r0[j] = *(unsigned*)&h0; x2r0[j] = *(unsigned*)&e0;
                x1r1[j] = *(unsigned*)&h1; x2r1[j] = *(unsigned*)&e1;
            }
            #pragma unroll
            for (int s4 = 0; s4 < 4; s4++) {
                const int s = split * 128 + c * 4 + s4;
                const uint4* B1 = g_Wfrag4 + ((size_t)s * 4) * 32 + lane;
                const int k0 = 2 * s4, k1 = 2 * s4 + 1;
                #pragma unroll
                for (int tp = 0; tp < 4; tp++) {
                    uint4 bv = B1[tp * 32];
                    MMA(acc[2*tp],   x1r0[k0], x1r1[k0], x1r0[k1], x1r1[k1], bv.x, bv.y);
                    MMA(acc[2*tp],   x2r0[k0], x2r1[k0], x2r0[k1], x2r1[k1], bv.x, bv.y);
                    MMA(acc[2*tp+1], x1r0[k0], x1r1[k0], x1r0[k1], x1r1[k1], bv.z, bv.w);
                    MMA(acc[2*tp+1], x2r0[k0], x2r1[k0], x2r0[k1], x2r1[k1], bv.z, bv.w);
                }
            }
        }

        // store fp32 partials (token-major)
        float* base = g_part + (size_t)split * N_TOK * N_EXP
                    + (size_t)(m_base + wid * 16 + g) * N_EXP;
        #pragma unroll
        for (int t = 0; t < 8; t++) {
            int c0 = t * 8 + q * 2;
            *(float2*)(base + c0)             = make_float2(acc[t][0], acc[t][1]);
            *(float2*)(base + 8 * N_EXP + c0) = make_float2(acc[t][2], acc[t][3]);
        }
    }

    // last CTA of the tile reduces + top-3 + softmax + flags
    __threadfence();
    __syncthreads();
    if (tid == 0) s_old = atomicAdd(&g_tilecnt[tile], 1);
    __syncthreads();
    if (s_old == 1) {
        __threadfence();
        if (tid < 64) {
            int token = m_base + tid;
            const float4* r0 = (const float4*)(g_part + (size_t)token * N_EXP);
            const float4* r1 = (const float4*)(g_part + (size_t)(N_TOK + token) * N_EXP);
            float mv = -CUDART_INF_F, sv = -CUDART_INF_F, tv = -CUDART_INF_F;
            int mi = 0, si = 0;
            #pragma unroll
            for (int ch = 0; ch < 16; ch++) {
                float4 a = r0[ch], b = r1[ch];
                float v4[4] = {a.x + b.x, a.y + b.y, a.z + b.z, a.w + b.w};
                #pragma unroll
                for (int j = 0; j < 4; j++) {
                    float v = v4[j];
                    int i = ch * 4 + j;
                    if (v > mv)      { tv = sv; sv = mv; si = mi; mv = v; mi = i; }
                    else if (v > sv) { tv = sv; sv = v;  si = i; }
                    else if (v > tv) { tv = v; }
                }
            }
            float t   = expf(sv - mv);
            float inv = 1.0f / (1.0f + t);
            g_topp[2 * token]     = inv;
            g_topp[2 * token + 1] = t * inv;
            g_topidx[2 * token]     = mi;
            g_topidx[2 * token + 1] = si;
            if (mv - sv < TH_GAP || sv - tv < TH_GAP) {
                int p = atomicAdd(&g_nflag, 1);
                if (p < N_TOK) g_flaglist[p] = token;
            }
        }
    }
    gridbar(GRID);

    // ---- phase 1: exact fp32 fixup of flagged tokens (candidate-based) ----
    {
        __shared__ float srow[N_EXP];
        __shared__ float sexact[16];
        __shared__ int   scand[16];
        __shared__ int   sncand;
        __shared__ float ssv;
        int nf = g_nflag;
        if (nf > N_TOK) nf = N_TOK;
        for (int f = blockIdx.x; f < nf; f += GRID) {
            int token = g_flaglist[f];
            if (tid < N_EXP)
                srow[tid] = g_part[(size_t)token * N_EXP + tid]
                          + g_part[(size_t)(N_TOK + token) * N_EXP + tid];
            if (tid == 0) sncand = 0;
            __syncthreads();
            if (tid == 0) {
                float mv = -CUDART_INF_F, sv = -CUDART_INF_F;
                for (int i = 0; i < N_EXP; i++) {
                    float v = srow[i];
                    if (v > mv) { sv = mv; mv = v; }
                    else if (v > sv) sv = v;
                }
                ssv = sv;
            }
            __syncthreads();
            if (tid < N_EXP && srow[tid] >= ssv - 2.0f * TH_GAP) {
                int p = atomicAdd(&sncand, 1);
                if (p < 16) scand[p] = tid;
            }
            __syncthreads();
            int nc = sncand < 16 ? sncand : 16;
            for (int ci = wid; ci < nc; ci += 4) {
                int e = scand[ci];
                const float4* xr = (const float4*)(X + (size_t)token * IN_FEAT);
                const float4* wr = (const float4*)(W + (size_t)e * IN_FEAT);
                float a0 = 0.f, a1 = 0.f, a2 = 0.f, a3 = 0.f;
                #pragma unroll 2
                for (int k = lane; k < IN_FEAT / 4; k += 128) {
                    float4 xa = xr[k],      wa = wr[k];
                    float4 xb = xr[k + 32], wb = wr[k + 32];
                    float4 xc = xr[k + 64], wc = wr[k + 64];
                    float4 xd = xr[k + 96], wd = wr[k + 96];
                    a0 = fmaf(xa.x, wa.x, a0); a0 = fmaf(xa.y, wa.y, a0);
                    a0 = fmaf(xa.z, wa.z, a0); a0 = fmaf(xa.w, wa.w, a0);
                    a1 = fmaf(xb.x, wb.x, a1); a1 = fmaf(xb.y, wb.y, a1);
                    a1 = fmaf(xb.z, wb.z, a1); a1 = fmaf(xb.w, wb.w, a1);
                    a2 = fmaf(xc.x, wc.x, a2); a2 = fmaf(xc.y, wc.y, a2);
                    a2 = fmaf(xc.z, wc.z, a2); a2 = fmaf(xc.w, wc.w, a2);
                    a3 = fmaf(xd.x, wd.x, a3); a3 = fmaf(xd.y, wd.y, a3);
                    a3 = fmaf(xd.z, wd.z, a3); a3 = fmaf(xd.w, wd.w, a3);
                }
                float acc = (a0 + a1) + (a2 + a3);
                #pragma unroll
                for (int off = 16; off; off >>= 1)
                    acc += __shfl_xor_sync(0xFFFFFFFFu, acc, off);
                if (lane == 0) sexact[ci] = acc;
            }
            __syncthreads();
            if (tid == 0) {
                float mv = -CUDART_INF_F, sv = -CUDART_INF_F;
                int mi = N_EXP, si = N_EXP;
                for (int ci = 0; ci < nc; ci++) {
                    int e = scand[ci];
                    float v = sexact[ci];
                    if (v > mv || (v == mv && e < mi)) { sv = mv; si = mi; mv = v; mi = e; }
                    else if (v > sv || (v == sv && e < si)) { sv = v; si = e; }
                }
                float t = expf(sv - mv), inv = 1.0f / (1.0f + t);
                g_topp[2 * token] = inv;  g_topp[2 * token + 1] = t * inv;
                g_topidx[2 * token] = mi; g_topidx[2 * token + 1] = si;
            }
            __syncthreads();
        }
    }
    gridbar(2 * GRID);

    // ---- phase 2: scatter (histogram + per-expert lists) + optimistic out ----
    {
        __shared__ int scnt[N_EXP];
        __shared__ int sbase[N_EXP];
        int token = blockIdx.x * 32 + (tid & 31);    // 512 blk x 32 tokens
        bool active = (tid < 32);
        if (tid < N_EXP) scnt[tid] = 0;
        __syncthreads();
        int e1 = 0, e2 = 0, p1 = 0, p2 = 0;
        if (active) {
            e1 = g_topidx[2 * token]; e2 = g_topidx[2 * token + 1];
            p1 = atomicAdd(&scnt[e1], 1);
            p2 = atomicAdd(&scnt[e2], 1);
        }
        __syncthreads();
        if (tid < N_EXP) sbase[tid] = atomicAdd(&g_counts[tid], scnt[tid]);
        __syncthreads();
        if (active) {
            g_elist[(size_t)e1 * N_TOK + sbase[e1] + p1] = 2 * token;
            g_elist[(size_t)e2 * N_TOK + sbase[e2] + p2] = 2 * token + 1;
            // optimistic output (patched by cap phase on overflow only)
            out[2 * token]                 = g_topp[2 * token];
            out[2 * token + 1]             = g_topp[2 * token + 1];
            out[2 * N_TOK + 2 * token]     = (float)e1;
            out[2 * N_TOK + 2 * token + 1] = (float)e2;
        }
    }
    gridbar(3 * GRID);

    // ---- phase 3: counts output + capacity patch (blocks 0..63) ----
    {
        int e = blockIdx.x;
        if (e < N_EXP) {
            int cnt = g_counts[e];
            if (tid == 0) out[4 * N_TOK + e] = (float)cnt;
            if (cnt > CAPACITY) {
                const int* lst = g_elist + (size_t)e * N_TOK;
                for (int i = tid; i < cnt; i += 128) {
                    int enc_i = lst[i];
                    float pi = g_topp[enc_i];
                    int ti = enc_i >> 1;
                    int rank = 0;
                    for (int j = 0; j < cnt; ++j) {
                        int enc_j = lst[j];
                        float pj = g_topp[enc_j];
                        int tj = enc_j >> 1;
                        rank += (pj > pi) || (pj == pi && tj < ti);
                    }
                    if (rank >= CAPACITY) {
                        out[enc_i]           = 0.0f;
                        out[2 * N_TOK + enc_i] = 2147483648.0f;
                    }
                }
            }
        }
    }
}

// ---------------------------------------------------------------------------
extern "C" void kernel_launch(void* const* d_in, const int* in_sizes, int n_in,
                              void* d_out, int out_size) {
    const float* X = (const float*)d_in[0];   // [16384, 4096]
    const float* W = (const float*)d_in[1];   // [64, 4096]
    float* out = (float*)d_out;

    prep_kernel<<<256, 256>>>(W);                             // 1 (incl. init)
    gemm_kernel<<<GRID, 128>>>(X, W, out);                    // 2 (everything)
}